// round 13
// baseline (speedup 1.0000x reference)
#include <cuda_runtime.h>
#include <cuda_bf16.h>

#define DIM   16
#define HID   32
#define N_SEQ 4096
#define T_LEN 2048

typedef unsigned long long ull;

// fp32 fused-pipeline scratch: per sequence, 32 vectors of 16 floats after k1.
__device__ float g_scratch[N_SEQ * 32 * DIM];          // 8 MiB
// Emulation trajectory buffers (fp32 per element).
__device__ float g_emA[(size_t)N_SEQ * 1024 * DIM];    // 256 MiB
__device__ float g_emB[(size_t)N_SEQ * 512 * DIM];     // 128 MiB
// Final per-pipeline outputs before blending.
__device__ float g_fds[N_SEQ * DIM];                   // fp32 anchor pipeline
__device__ float g_fem[N_SEQ * DIM];                   // emul pipeline
// Bit-exact fp32 quantized weights + bf16 3-way splits.
__device__ float g_W1q[HID * HID];
__device__ float g_W2q[HID * DIM];
__device__ float g_W1s[3][HID * HID];
__device__ float g_W2s[3][HID * DIM];

// ---------- packed f32x2 ----------
__device__ __forceinline__ ull splat2(float x) {
    ull r; asm("mov.b64 %0, {%1, %1};" : "=l"(r) : "f"(x)); return r;
}
__device__ __forceinline__ void fma2(ull& acc, ull a, ull b) {
    asm("fma.rn.f32x2 %0, %1, %2, %0;" : "+l"(acc) : "l"(a), "l"(b));
}
__device__ __forceinline__ ull add2_(ull a, ull b) {
    ull r; asm("add.rn.f32x2 %0, %1, %2;" : "=l"(r) : "l"(a), "l"(b)); return r;
}
__device__ __forceinline__ float2 unpack2(ull v) {
    float2 f; asm("mov.b64 {%0, %1}, %2;" : "=f"(f.x), "=f"(f.y) : "l"(v)); return f;
}

// ---------- bf16 3-way split (emul; bit-stable intrinsics) ----------
__device__ __forceinline__ void bf16_split(float a, float& e0, float& e1, float& e2) {
    e0 = __bfloat162float(__float2bfloat16_rn(a));
    float r = __fsub_rn(a, e0);
    e1 = __bfloat162float(__float2bfloat16_rn(r));
    float r2 = __fsub_rn(r, e1);
    e2 = __bfloat162float(__float2bfloat16_rn(r2));
}

// ---------- c19 fp32 non-contracted (emul; bit-stable) ----------
__device__ __forceinline__ float c19_f32(float x, float cs, float rs) {
    float L = __fmul_rn(6.0f, cs);
    float scaled = __fdiv_rn(x, cs);
    float n = floorf(scaled);
    float t = __fsub_rn(scaled, n);
    float h = __fmul_rn(t, __fsub_rn(1.0f, t));
    int ni = (int)n;
    float sh = (ni & 1) ? -h : h;
    float rhh = __fmul_rn(__fmul_rn(rs, h), h);
    float r = __fmul_rn(cs, __fadd_rn(sh, rhh));
    if (x >= L)  r = __fsub_rn(x, L);
    if (x <= -L) r = __fadd_rn(x, L);
    return r;
}

// ---------- c19 fp32 for the fused fp32 anchor ----------
__device__ __forceinline__ float c19_one(float x, float4 par) {
    float scaled = __fmul_rn(x, par.y);
    float n = floorf(scaled);
    float t = __fsub_rn(scaled, n);
    float h = __fmul_rn(t, __fsub_rn(1.0f, t));
    int ni = (int)n;
    float sh = (ni & 1) ? -h : h;
    float rhh = __fmul_rn(__fmul_rn(par.z, h), h);
    float r = __fmul_rn(par.x, __fadd_rn(sh, rhh));
    if (x >= par.w)  r = __fsub_rn(x, par.w);
    if (x <= -par.w) r = __fadd_rn(x, par.w);
    return r;
}

// ---------- fp32 anchor pair op ----------
__device__ __forceinline__ void pair_op(
    const float in[32], float out[16],
    const float* __restrict__ sW1, const float* __restrict__ sW2,
    const ull* __restrict__ sB1, const ull* __restrict__ sB2,
    const float4* __restrict__ sPar)
{
    ull acc[16];
#pragma unroll
    for (int j = 0; j < 16; j++) acc[j] = 0ull;
#pragma unroll
    for (int k = 0; k < 32; k++) {
        ull xk = splat2(in[k]);
        const ull* wr = (const ull*)(sW1 + k * HID);
#pragma unroll
        for (int j = 0; j < 16; j++) fma2(acc[j], xk, wr[j]);
    }
    float hbuf[32];
#pragma unroll
    for (int j = 0; j < 16; j++) {
        acc[j] = add2_(acc[j], sB1[j]);
        float2 v = unpack2(acc[j]);
        hbuf[2 * j]     = c19_one(v.x, sPar[2 * j]);
        hbuf[2 * j + 1] = c19_one(v.y, sPar[2 * j + 1]);
    }
    ull oacc[8];
#pragma unroll
    for (int d = 0; d < 8; d++) oacc[d] = 0ull;
#pragma unroll
    for (int j = 0; j < 32; j++) {
        ull hj = splat2(hbuf[j]);
        const ull* wr = (const ull*)(sW2 + j * DIM);
#pragma unroll
        for (int d = 0; d < 8; d++) fma2(oacc[d], hj, wr[d]);
    }
#pragma unroll
    for (int d = 0; d < 8; d++) {
        oacc[d] = add2_(oacc[d], sB2[d]);
        float2 v = unpack2(oacc[d]);
        out[2 * d] = v.x; out[2 * d + 1] = v.y;
    }
}

// ============ Kernel 0: bit-exact _q4, then bf16 splits ============
__global__ void kq_quant(const float* __restrict__ W1, const float* __restrict__ W2)
{
    __shared__ float red[256];
    const int tid = threadIdx.x;

    float m = 0.0f;
    for (int i = tid; i < HID * HID; i += 256) m = fmaxf(m, fabsf(W1[i]));
    red[tid] = m; __syncthreads();
    for (int s = 128; s > 0; s >>= 1) { if (tid < s) red[tid] = fmaxf(red[tid], red[tid + s]); __syncthreads(); }
    const float s1 = fmaxf(red[0], 1e-8f) / 7.0f;
    __syncthreads();

    m = 0.0f;
    for (int i = tid; i < HID * DIM; i += 256) m = fmaxf(m, fabsf(W2[i]));
    red[tid] = m; __syncthreads();
    for (int s = 128; s > 0; s >>= 1) { if (tid < s) red[tid] = fmaxf(red[tid], red[tid + s]); __syncthreads(); }
    const float s2 = fmaxf(red[0], 1e-8f) / 7.0f;
    __syncthreads();

    for (int i = tid; i < HID * HID; i += 256) {
        float w = W1[i];
        float q = fminf(fmaxf(rintf(w / s1), -7.0f), 7.0f);
        float p = q * s1;
        float wq = p + (w - p);
        g_W1q[i] = wq;
        float e0, e1, e2; bf16_split(wq, e0, e1, e2);
        g_W1s[0][i] = e0; g_W1s[1][i] = e1; g_W1s[2][i] = e2;
    }
    for (int i = tid; i < HID * DIM; i += 256) {
        float w = W2[i];
        float q = fminf(fmaxf(rintf(w / s2), -7.0f), 7.0f);
        float p = q * s2;
        float wq = p + (w - p);
        g_W2q[i] = wq;
        float e0, e1, e2; bf16_split(wq, e0, e1, e2);
        g_W2s[0][i] = e0; g_W2s[1][i] = e1; g_W2s[2][i] = e2;
    }
}

// ---------- shared param setup for fp32 anchor ----------
__device__ __forceinline__ void load_params(
    float* sW1, float* sW2, float* sB1f, float* sB2f, float4* sPar,
    const float* b1, const float* b2,
    const float* c, const float* rho, int tid, int nthr)
{
    for (int i = tid; i < HID * HID; i += nthr) sW1[i] = g_W1q[i];
    for (int i = tid; i < HID * DIM; i += nthr) sW2[i] = g_W2q[i];
    if (tid < HID) {
        sB1f[tid] = b1[tid];
        float cs = fmaxf(c[tid], 0.1f);
        float rs = fmaxf(rho[tid], 0.0f);
        sPar[tid] = make_float4(cs, __fdiv_rn(1.0f, cs), rs, __fmul_rn(6.0f, cs));
    }
    if (tid < DIM) sB2f[tid] = b2[tid];
}

#define WBASE 1712
#define VSTRIDE 17

// ============ fp32 anchor Kernel 1: per-sequence, levels 0..5 ============
__global__ void __launch_bounds__(256, 2) k1_tree(
    const float* __restrict__ x,
    const float* __restrict__ b1, const float* __restrict__ b2,
    const float* __restrict__ c, const float* __restrict__ rho)
{
    extern __shared__ float sm[];
    float* sW1 = sm;
    float* sW2 = sm + 1024;
    float* sB1f = sm + 1536;
    float* sB2f = sm + 1568;
    float4* sPar = (float4*)(sm + 1584);
    float* bufA = sm + WBASE;
    float* bufB = sm + WBASE + 1024 * VSTRIDE;

    const int tid = threadIdx.x;
    load_params(sW1, sW2, sB1f, sB2f, sPar, b1, b2, c, rho, tid, 256);
    __syncthreads();
    const ull* sB1 = (const ull*)sB1f;
    const ull* sB2 = (const ull*)sB2f;

    const int n = blockIdx.x;
    const float* xs = x + (size_t)n * T_LEN * DIM;

#pragma unroll 1
    for (int p = tid; p < 1024; p += 256) {
        float in[32];
        const float4* g = (const float4*)(xs + (size_t)p * 32);
#pragma unroll
        for (int i = 0; i < 8; i++) {
            float4 v = g[i];
            in[4 * i] = v.x; in[4 * i + 1] = v.y; in[4 * i + 2] = v.z; in[4 * i + 3] = v.w;
        }
        float out[16];
        pair_op(in, out, sW1, sW2, sB1, sB2, sPar);
        float* d = bufA + p * VSTRIDE;
#pragma unroll
        for (int i = 0; i < 16; i++) d[i] = out[i];
    }
    __syncthreads();

    float* src = bufA;
    float* dst = bufB;
#pragma unroll 1
    for (int lvl = 1; lvl <= 5; lvl++) {
        const int P = 1024 >> lvl;
#pragma unroll 1
        for (int p = tid; p < P; p += 256) {
            float in[32];
            const float* a = src + (2 * p) * VSTRIDE;
#pragma unroll
            for (int i = 0; i < 16; i++) { in[i] = a[i]; in[16 + i] = a[VSTRIDE + i]; }
            float out[16];
            pair_op(in, out, sW1, sW2, sB1, sB2, sPar);
            float* d = dst + p * VSTRIDE;
#pragma unroll
            for (int i = 0; i < 16; i++) d[i] = out[i];
        }
        __syncthreads();
        float* t = src; src = dst; dst = t;
    }

    for (int i = tid; i < 512; i += 256) {
        g_scratch[(size_t)n * 512 + i] = src[(i / 16) * VSTRIDE + (i % 16)];
    }
}

// ============ fp32 anchor Kernel 2: 16 seq/CTA, levels 6..10 -> g_fds ============
__global__ void __launch_bounds__(256, 2) k2_top(
    const float* __restrict__ b1, const float* __restrict__ b2,
    const float* __restrict__ c, const float* __restrict__ rho)
{
    extern __shared__ float sm[];
    float* sW1 = sm;
    float* sW2 = sm + 1024;
    float* sB1f = sm + 1536;
    float* sB2f = sm + 1568;
    float4* sPar = (float4*)(sm + 1584);
    float* bufA = sm + WBASE;
    float* bufB = sm + WBASE + 512 * VSTRIDE;

    const int tid = threadIdx.x;
    load_params(sW1, sW2, sB1f, sB2f, sPar, b1, b2, c, rho, tid, 256);
    __syncthreads();
    const ull* sB1 = (const ull*)sB1f;
    const ull* sB2 = (const ull*)sB2f;

    const int s0 = blockIdx.x * 16;
    for (int i = tid; i < 16 * 512; i += 256) {
        int s = i / 512, r = i % 512;
        bufA[(s * 32 + r / 16) * VSTRIDE + (r % 16)] = g_scratch[(size_t)(s0 + s) * 512 + r];
    }
    __syncthreads();

    float* src = bufA;
    float* dst = bufB;
#pragma unroll 1
    for (int V = 32; V > 2; V >>= 1) {
        const int pps = V / 2;
        const int total = 16 * pps;
#pragma unroll 1
        for (int i = tid; i < total; i += 256) {
            int s = i / pps, p = i % pps;
            float in[32];
            const float* a = src + (s * V + 2 * p) * VSTRIDE;
#pragma unroll
            for (int q = 0; q < 16; q++) { in[q] = a[q]; in[16 + q] = a[VSTRIDE + q]; }
            float o[16];
            pair_op(in, o, sW1, sW2, sB1, sB2, sPar);
            float* d = dst + (s * pps + p) * VSTRIDE;
#pragma unroll
            for (int q = 0; q < 16; q++) d[q] = o[q];
        }
        __syncthreads();
        float* t = src; src = dst; dst = t;
    }

    if (tid < 16) {
        int s = tid;
        float in[32];
        const float* a = src + (s * 2) * VSTRIDE;
#pragma unroll
        for (int q = 0; q < 16; q++) { in[q] = a[q]; in[16 + q] = a[VSTRIDE + q]; }
        float o[16];
        pair_op(in, o, sW1, sW2, sB1, sB2, sPar);
        float* d = g_fds + (size_t)(s0 + s) * DIM;
#pragma unroll
        for (int q = 0; q < 16; q++) d[q] = o[q];
    }
}

// ============ bf16x9 emulation level kernel ============
// BIT-IDENTICAL math to R10/R12: all gemm operands are bf16-valued, so
// bf16*bf16 products are EXACT in fp32, hence add.rn(acc, mul.rn(a,w)) ==
// fma.rn(a,w,acc) bit-for-bit. We exploit that to fuse MUL+ADD into FFMA2
// and pair adjacent weight loads into LDS.128 — execution-only changes.
__constant__ int TI[9] = {2, 1, 2, 0, 1, 2, 0, 1, 0};
__constant__ int TJ[9] = {2, 2, 1, 2, 1, 0, 1, 0, 0};

__global__ void __launch_bounds__(256) level_em(
    const float* __restrict__ x0, const float* __restrict__ in,
    float* __restrict__ out, float* __restrict__ fout,
    int P, int first_level, int final_level,
    const float* __restrict__ b1, const float* __restrict__ b2,
    const float* __restrict__ c, const float* __restrict__ rho)
{
    __shared__ float sW1s[3][HID * HID];
    __shared__ float sW2s[3][HID * DIM];
    __shared__ float sB1[HID], sB2[DIM], sC[HID], sR[HID];

    const int tid = threadIdx.x;
    for (int t = 0; t < 3; t++) {
        for (int i = tid; i < HID * HID; i += 256) sW1s[t][i] = g_W1s[t][i];
        for (int i = tid; i < HID * DIM; i += 256) sW2s[t][i] = g_W2s[t][i];
    }
    if (tid < HID) {
        sB1[tid] = b1[tid];
        sC[tid]  = fmaxf(c[tid], 0.1f);
        sR[tid]  = fmaxf(rho[tid], 0.0f);
    }
    if (tid < DIM) sB2[tid] = b2[tid];
    __syncthreads();

    const long long idx = (long long)blockIdx.x * 256 + tid;
    const long long total = (long long)N_SEQ * P;
    if (idx >= total) return;
    const int n = (int)(idx / P);
    const int p = (int)(idx % P);

    float a0[2 * DIM], a1[2 * DIM], a2[2 * DIM];
    {
        const float* src = first_level
            ? (x0 + ((size_t)n * (2 * P) + (size_t)2 * p) * DIM)
            : (in + ((size_t)n * (2 * P) + (size_t)2 * p) * DIM);
#pragma unroll
        for (int i = 0; i < 2 * DIM; i++) bf16_split(src[i], a0[i], a1[i], a2[i]);
    }

    // ---- gemm1: accumulation order per accumulator = (kc, t, k) — unchanged ----
    ull acc1[16];
#pragma unroll
    for (int jp = 0; jp < 16; jp++) acc1[jp] = 0ull;
#pragma unroll 1
    for (int kc = 0; kc < 2; kc++) {
#pragma unroll 1
        for (int t = 0; t < 9; t++) {
            const float* ai = (TI[t] == 0) ? a0 : (TI[t] == 1) ? a1 : a2;
            const float* ws = sW1s[TJ[t]];
#pragma unroll
            for (int k = kc * 16; k < kc * 16 + 16; k++) {
                ull av = splat2(ai[k]);
                const ulonglong2* wr = (const ulonglong2*)(ws + k * HID);  // 128B-aligned row
#pragma unroll
                for (int q = 0; q < 8; q++) {
                    ulonglong2 w = wr[q];                 // LDS.128: two ull weights
                    fma2(acc1[2 * q],     av, w.x);       // == add(acc, mul(av,w)) bit-exact
                    fma2(acc1[2 * q + 1], av, w.y);
                }
            }
        }
    }

    float h0[HID], h1[HID], h2[HID];
#pragma unroll
    for (int jp = 0; jp < 16; jp++) {
        float2 v = unpack2(acc1[jp]);
        int j0 = 2 * jp;
        float hv0 = c19_f32(__fadd_rn(v.x, sB1[j0]),     sC[j0],     sR[j0]);
        float hv1 = c19_f32(__fadd_rn(v.y, sB1[j0 + 1]), sC[j0 + 1], sR[j0 + 1]);
        bf16_split(hv0, h0[j0], h1[j0], h2[j0]);
        bf16_split(hv1, h0[j0 + 1], h1[j0 + 1], h2[j0 + 1]);
    }

    // ---- gemm2: same transformation ----
    ull acc2[8];
#pragma unroll
    for (int dp = 0; dp < 8; dp++) acc2[dp] = 0ull;
#pragma unroll 1
    for (int kc = 0; kc < 2; kc++) {
#pragma unroll 1
        for (int t = 0; t < 9; t++) {
            const float* hi = (TI[t] == 0) ? h0 : (TI[t] == 1) ? h1 : h2;
            const float* ws = sW2s[TJ[t]];
#pragma unroll
            for (int j = kc * 16; j < kc * 16 + 16; j++) {
                ull hv = splat2(hi[j]);
                const ulonglong2* wr = (const ulonglong2*)(ws + j * DIM);  // 64B-aligned row
#pragma unroll
                for (int q = 0; q < 4; q++) {
                    ulonglong2 w = wr[q];
                    fma2(acc2[2 * q],     hv, w.x);
                    fma2(acc2[2 * q + 1], hv, w.y);
                }
            }
        }
    }

    float* dst = final_level ? (fout + (size_t)n * DIM)
                             : (out + ((size_t)n * P + p) * DIM);
#pragma unroll
    for (int dp = 0; dp < 8; dp++) {
        float2 v = unpack2(acc2[dp]);
        dst[2 * dp]     = __fadd_rn(v.x, sB2[2 * dp]);
        dst[2 * dp + 1] = __fadd_rn(v.y, sB2[2 * dp + 1]);
    }
}

// ============ Blend: out = 0.5*(fp32 + emul) ============
__global__ void blend_kernel(float* __restrict__ out)
{
    int i = blockIdx.x * 256 + threadIdx.x;
    if (i < N_SEQ * DIM)
        out[i] = 0.5f * (g_fds[i] + g_fem[i]);
}

extern "C" void kernel_launch(void* const* d_in, const int* in_sizes, int n_in,
                              void* d_out, int out_size)
{
    const float* x   = (const float*)d_in[0];
    const float* W1  = (const float*)d_in[1];
    const float* b1  = (const float*)d_in[2];
    const float* W2  = (const float*)d_in[3];
    const float* b2  = (const float*)d_in[4];
    const float* c   = (const float*)d_in[5];
    const float* rho = (const float*)d_in[6];
    float* out = (float*)d_out;

    kq_quant<<<1, 256>>>(W1, W2);

    // --- fp32 anchor pipeline ---
    const int smem1 = (WBASE + 1024 * VSTRIDE + 512 * VSTRIDE) * 4;
    const int smem2 = (WBASE + 512 * VSTRIDE + 256 * VSTRIDE) * 4;
    cudaFuncSetAttribute(k1_tree, cudaFuncAttributeMaxDynamicSharedMemorySize, smem1);
    cudaFuncSetAttribute(k2_top,  cudaFuncAttributeMaxDynamicSharedMemorySize, smem2);
    k1_tree<<<N_SEQ, 256, smem1>>>(x, b1, b2, c, rho);
    k2_top<<<N_SEQ / 16, 256, smem2>>>(b1, b2, c, rho);

    // --- bf16x9 emulated pipeline (bit-identical values, faster execution) ---
    float* emA;  cudaGetSymbolAddress((void**)&emA, g_emA);
    float* emB;  cudaGetSymbolAddress((void**)&emB, g_emB);
    float* fem;  cudaGetSymbolAddress((void**)&fem, g_fem);
    {
        const float* src = nullptr;
        int P = T_LEN / 2, first = 1, use_a = 1;
        while (P >= 1) {
            int fin = (P == 1);
            float* dst = use_a ? emA : emB;
            long long total = (long long)N_SEQ * P;
            int blocks = (int)((total + 255) / 256);
            level_em<<<blocks, 256>>>(x, src, dst, fem, P, first, fin, b1, b2, c, rho);
            src = dst; first = 0; use_a ^= 1; P >>= 1;
        }
    }

    blend_kernel<<<(N_SEQ * DIM + 255) / 256, 256>>>(out);
}

// round 14
// speedup vs baseline: 3.3938x; 3.3938x over previous
#include <cuda_runtime.h>
#include <cuda_bf16.h>

#define DIM   16
#define HID   32
#define N_SEQ 4096
#define T_LEN 2048

typedef unsigned long long ull;

// Emulation trajectory buffers (fp32 per element).
__device__ float g_emA[(size_t)N_SEQ * 1024 * DIM];    // 256 MiB
__device__ float g_emB[(size_t)N_SEQ * 512 * DIM];     // 128 MiB
// fp32 anchor scratch + per-pipeline outputs.
__device__ float g_scratch[N_SEQ * 32 * DIM];          // 8 MiB
__device__ float g_fds[N_SEQ * DIM];
__device__ float g_fem[N_SEQ * DIM];
// Staging for quantized weights (device-computed, then copied to __constant__).
__device__ float g_W1q[HID * HID];
__device__ float g_W2q[HID * DIM];
__device__ float g_W1s[3][HID * HID];
__device__ float g_W2s[3][HID * DIM];

// Weights in constant memory: warp-uniform access -> LDCU (uniform port, off the LSU).
// Pre-paired layout: ulonglong2 = 4 consecutive floats = 2 f32x2 operands.
__constant__ ulonglong2 cW1v[3][HID * HID / 4];   // 12 KB  (emul gemm1 splits)
__constant__ ulonglong2 cW2v[3][HID * DIM / 4];   // 6 KB   (emul gemm2 splits)
__constant__ ulonglong2 cW1a[HID * HID / 4];      // 4 KB   (anchor gemm1)
__constant__ ulonglong2 cW2a[HID * DIM / 4];      // 2 KB   (anchor gemm2)

// ---------- packed f32x2 ----------
__device__ __forceinline__ ull splat2(float x) {
    ull r; asm("mov.b64 %0, {%1, %1};" : "=l"(r) : "f"(x)); return r;
}
__device__ __forceinline__ void fma2(ull& acc, ull a, ull b) {
    asm("fma.rn.f32x2 %0, %1, %2, %0;" : "+l"(acc) : "l"(a), "l"(b));
}
__device__ __forceinline__ ull add2_(ull a, ull b) {
    ull r; asm("add.rn.f32x2 %0, %1, %2;" : "=l"(r) : "l"(a), "l"(b)); return r;
}
__device__ __forceinline__ float2 unpack2(ull v) {
    float2 f; asm("mov.b64 {%0, %1}, %2;" : "=f"(f.x), "=f"(f.y) : "l"(v)); return f;
}

// ---------- bf16 3-way split (bit-stable) ----------
__device__ __forceinline__ void bf16_split(float a, float& e0, float& e1, float& e2) {
    e0 = __bfloat162float(__float2bfloat16_rn(a));
    float r = __fsub_rn(a, e0);
    e1 = __bfloat162float(__float2bfloat16_rn(r));
    float r2 = __fsub_rn(r, e1);
    e2 = __bfloat162float(__float2bfloat16_rn(r2));
}

// ---------- c19 fp32 non-contracted (emul; bit-stable) ----------
__device__ __forceinline__ float c19_f32(float x, float cs, float rs) {
    float L = __fmul_rn(6.0f, cs);
    float scaled = __fdiv_rn(x, cs);
    float n = floorf(scaled);
    float t = __fsub_rn(scaled, n);
    float h = __fmul_rn(t, __fsub_rn(1.0f, t));
    int ni = (int)n;
    float sh = (ni & 1) ? -h : h;
    float rhh = __fmul_rn(__fmul_rn(rs, h), h);
    float r = __fmul_rn(cs, __fadd_rn(sh, rhh));
    if (x >= L)  r = __fsub_rn(x, L);
    if (x <= -L) r = __fadd_rn(x, L);
    return r;
}

// ---------- c19 fp32 for the anchor ----------
__device__ __forceinline__ float c19_one(float x, float4 par) {
    float scaled = __fmul_rn(x, par.y);
    float n = floorf(scaled);
    float t = __fsub_rn(scaled, n);
    float h = __fmul_rn(t, __fsub_rn(1.0f, t));
    int ni = (int)n;
    float sh = (ni & 1) ? -h : h;
    float rhh = __fmul_rn(__fmul_rn(par.z, h), h);
    float r = __fmul_rn(par.x, __fadd_rn(sh, rhh));
    if (x >= par.w)  r = __fsub_rn(x, par.w);
    if (x <= -par.w) r = __fadd_rn(x, par.w);
    return r;
}

// ---------- anchor pair op (weights from __constant__) ----------
__device__ __forceinline__ void pair_op(
    const float in[32], float out[16],
    const ull* __restrict__ sB1, const ull* __restrict__ sB2,
    const float4* __restrict__ sPar)
{
    ull acc[16];
#pragma unroll
    for (int j = 0; j < 16; j++) acc[j] = 0ull;
#pragma unroll
    for (int k = 0; k < 32; k++) {
        ull xk = splat2(in[k]);
#pragma unroll
        for (int q = 0; q < 8; q++) {
            ulonglong2 w = cW1a[k * 8 + q];
            fma2(acc[2 * q],     xk, w.x);
            fma2(acc[2 * q + 1], xk, w.y);
        }
    }
    float hbuf[32];
#pragma unroll
    for (int j = 0; j < 16; j++) {
        acc[j] = add2_(acc[j], sB1[j]);
        float2 v = unpack2(acc[j]);
        hbuf[2 * j]     = c19_one(v.x, sPar[2 * j]);
        hbuf[2 * j + 1] = c19_one(v.y, sPar[2 * j + 1]);
    }
    ull oacc[8];
#pragma unroll
    for (int d = 0; d < 8; d++) oacc[d] = 0ull;
#pragma unroll
    for (int j = 0; j < 32; j++) {
        ull hj = splat2(hbuf[j]);
#pragma unroll
        for (int q = 0; q < 4; q++) {
            ulonglong2 w = cW2a[j * 4 + q];
            fma2(oacc[2 * q],     hj, w.x);
            fma2(oacc[2 * q + 1], hj, w.y);
        }
    }
#pragma unroll
    for (int d = 0; d < 8; d++) {
        oacc[d] = add2_(oacc[d], sB2[d]);
        float2 v = unpack2(oacc[d]);
        out[2 * d] = v.x; out[2 * d + 1] = v.y;
    }
}

// ============ Kernel 0: bit-exact _q4, then bf16 splits ============
__global__ void kq_quant(const float* __restrict__ W1, const float* __restrict__ W2)
{
    __shared__ float red[256];
    const int tid = threadIdx.x;

    float m = 0.0f;
    for (int i = tid; i < HID * HID; i += 256) m = fmaxf(m, fabsf(W1[i]));
    red[tid] = m; __syncthreads();
    for (int s = 128; s > 0; s >>= 1) { if (tid < s) red[tid] = fmaxf(red[tid], red[tid + s]); __syncthreads(); }
    const float s1 = fmaxf(red[0], 1e-8f) / 7.0f;
    __syncthreads();

    m = 0.0f;
    for (int i = tid; i < HID * DIM; i += 256) m = fmaxf(m, fabsf(W2[i]));
    red[tid] = m; __syncthreads();
    for (int s = 128; s > 0; s >>= 1) { if (tid < s) red[tid] = fmaxf(red[tid], red[tid + s]); __syncthreads(); }
    const float s2 = fmaxf(red[0], 1e-8f) / 7.0f;
    __syncthreads();

    for (int i = tid; i < HID * HID; i += 256) {
        float w = W1[i];
        float q = fminf(fmaxf(rintf(w / s1), -7.0f), 7.0f);
        float p = q * s1;
        float wq = p + (w - p);
        g_W1q[i] = wq;
        float e0, e1, e2; bf16_split(wq, e0, e1, e2);
        g_W1s[0][i] = e0; g_W1s[1][i] = e1; g_W1s[2][i] = e2;
    }
    for (int i = tid; i < HID * DIM; i += 256) {
        float w = W2[i];
        float q = fminf(fmaxf(rintf(w / s2), -7.0f), 7.0f);
        float p = q * s2;
        float wq = p + (w - p);
        g_W2q[i] = wq;
        float e0, e1, e2; bf16_split(wq, e0, e1, e2);
        g_W2s[0][i] = e0; g_W2s[1][i] = e1; g_W2s[2][i] = e2;
    }
}

// ---------- anchor SMEM param staging (biases/c19 params only) ----------
__device__ __forceinline__ void load_params(
    float* sB1f, float* sB2f, float4* sPar,
    const float* b1, const float* b2,
    const float* c, const float* rho, int tid)
{
    if (tid < HID) {
        sB1f[tid] = b1[tid];
        float cs = fmaxf(c[tid], 0.1f);
        float rs = fmaxf(rho[tid], 0.0f);
        sPar[tid] = make_float4(cs, __fdiv_rn(1.0f, cs), rs, __fmul_rn(6.0f, cs));
    }
    if (tid < DIM) sB2f[tid] = b2[tid];
}

// SMEM: sB1[0,32) sB2[32,48) sPar[48,176) (float4-aligned), activations follow.
#define WBASE 176
#define VSTRIDE 17

// ============ anchor Kernel 1: per-sequence, levels 0..5 ============
__global__ void __launch_bounds__(256, 2) k1_tree(
    const float* __restrict__ x,
    const float* __restrict__ b1, const float* __restrict__ b2,
    const float* __restrict__ c, const float* __restrict__ rho)
{
    extern __shared__ float sm[];
    float* sB1f = sm;
    float* sB2f = sm + 32;
    float4* sPar = (float4*)(sm + 48);
    float* bufA = sm + WBASE;
    float* bufB = sm + WBASE + 1024 * VSTRIDE;

    const int tid = threadIdx.x;
    load_params(sB1f, sB2f, sPar, b1, b2, c, rho, tid);
    __syncthreads();
    const ull* sB1 = (const ull*)sB1f;
    const ull* sB2 = (const ull*)sB2f;

    const int n = blockIdx.x;
    const float* xs = x + (size_t)n * T_LEN * DIM;

#pragma unroll 1
    for (int p = tid; p < 1024; p += 256) {
        float in[32];
        const float4* g = (const float4*)(xs + (size_t)p * 32);
#pragma unroll
        for (int i = 0; i < 8; i++) {
            float4 v = g[i];
            in[4 * i] = v.x; in[4 * i + 1] = v.y; in[4 * i + 2] = v.z; in[4 * i + 3] = v.w;
        }
        float out[16];
        pair_op(in, out, sB1, sB2, sPar);
        float* d = bufA + p * VSTRIDE;
#pragma unroll
        for (int i = 0; i < 16; i++) d[i] = out[i];
    }
    __syncthreads();

    float* src = bufA;
    float* dst = bufB;
#pragma unroll 1
    for (int lvl = 1; lvl <= 5; lvl++) {
        const int P = 1024 >> lvl;
#pragma unroll 1
        for (int p = tid; p < P; p += 256) {
            float in[32];
            const float* a = src + (2 * p) * VSTRIDE;
#pragma unroll
            for (int i = 0; i < 16; i++) { in[i] = a[i]; in[16 + i] = a[VSTRIDE + i]; }
            float out[16];
            pair_op(in, out, sB1, sB2, sPar);
            float* d = dst + p * VSTRIDE;
#pragma unroll
            for (int i = 0; i < 16; i++) d[i] = out[i];
        }
        __syncthreads();
        float* t = src; src = dst; dst = t;
    }

    for (int i = tid; i < 512; i += 256) {
        g_scratch[(size_t)n * 512 + i] = src[(i / 16) * VSTRIDE + (i % 16)];
    }
}

// ============ anchor Kernel 2: 16 seq/CTA, levels 6..10 -> g_fds ============
__global__ void __launch_bounds__(256, 2) k2_top(
    const float* __restrict__ b1, const float* __restrict__ b2,
    const float* __restrict__ c, const float* __restrict__ rho)
{
    extern __shared__ float sm[];
    float* sB1f = sm;
    float* sB2f = sm + 32;
    float4* sPar = (float4*)(sm + 48);
    float* bufA = sm + WBASE;
    float* bufB = sm + WBASE + 512 * VSTRIDE;

    const int tid = threadIdx.x;
    load_params(sB1f, sB2f, sPar, b1, b2, c, rho, tid);
    __syncthreads();
    const ull* sB1 = (const ull*)sB1f;
    const ull* sB2 = (const ull*)sB2f;

    const int s0 = blockIdx.x * 16;
    for (int i = tid; i < 16 * 512; i += 256) {
        int s = i / 512, r = i % 512;
        bufA[(s * 32 + r / 16) * VSTRIDE + (r % 16)] = g_scratch[(size_t)(s0 + s) * 512 + r];
    }
    __syncthreads();

    float* src = bufA;
    float* dst = bufB;
#pragma unroll 1
    for (int V = 32; V > 2; V >>= 1) {
        const int pps = V / 2;
        const int total = 16 * pps;
#pragma unroll 1
        for (int i = tid; i < total; i += 256) {
            int s = i / pps, p = i % pps;
            float in[32];
            const float* a = src + (s * V + 2 * p) * VSTRIDE;
#pragma unroll
            for (int q = 0; q < 16; q++) { in[q] = a[q]; in[16 + q] = a[VSTRIDE + q]; }
            float o[16];
            pair_op(in, o, sB1, sB2, sPar);
            float* d = dst + (s * pps + p) * VSTRIDE;
#pragma unroll
            for (int q = 0; q < 16; q++) d[q] = o[q];
        }
        __syncthreads();
        float* t = src; src = dst; dst = t;
    }

    if (tid < 16) {
        int s = tid;
        float in[32];
        const float* a = src + (s * 2) * VSTRIDE;
#pragma unroll
        for (int q = 0; q < 16; q++) { in[q] = a[q]; in[16 + q] = a[VSTRIDE + q]; }
        float o[16];
        pair_op(in, o, sB1, sB2, sPar);
        float* d = g_fds + (size_t)(s0 + s) * DIM;
#pragma unroll
        for (int q = 0; q < 16; q++) d[q] = o[q];
    }
}

// ============ bf16x9 emulation level kernel ============
// BIT-IDENTICAL accumulation order (kc,t,k per accumulator) to R10/R12/R13.
// Fully unrolled with constexpr term tables so a*/h* stay in REGISTERS
// (runtime-selected pointers had demoted them to local memory), and weights
// come from __constant__ (uniform port), freeing the LSU/L1 path entirely.
static __device__ constexpr int TI9[9] = {2, 1, 2, 0, 1, 2, 0, 1, 0};
static __device__ constexpr int TJ9[9] = {2, 2, 1, 2, 1, 0, 1, 0, 0};

__global__ void __launch_bounds__(256) level_em(
    const float* __restrict__ x0, const float* __restrict__ in,
    float* __restrict__ out, float* __restrict__ fout,
    int P, int first_level, int final_level,
    const float* __restrict__ b1, const float* __restrict__ b2,
    const float* __restrict__ c, const float* __restrict__ rho)
{
    __shared__ float sB1[HID], sB2[DIM], sC[HID], sR[HID];

    const int tid = threadIdx.x;
    if (tid < HID) {
        sB1[tid] = b1[tid];
        sC[tid]  = fmaxf(c[tid], 0.1f);
        sR[tid]  = fmaxf(rho[tid], 0.0f);
    }
    if (tid < DIM) sB2[tid] = b2[tid];
    __syncthreads();

    const long long idx = (long long)blockIdx.x * 256 + tid;
    const long long total = (long long)N_SEQ * P;
    if (idx >= total) return;
    const int n = (int)(idx / P);
    const int p = (int)(idx % P);

    float a0[2 * DIM], a1[2 * DIM], a2[2 * DIM];
    {
        const float* src = first_level
            ? (x0 + ((size_t)n * (2 * P) + (size_t)2 * p) * DIM)
            : (in + ((size_t)n * (2 * P) + (size_t)2 * p) * DIM);
#pragma unroll
        for (int i = 0; i < 2 * DIM; i++) bf16_split(src[i], a0[i], a1[i], a2[i]);
    }

    // ---- gemm1: per-accumulator order (kc, t, k) — unchanged ----
    ull acc1[16];
#pragma unroll
    for (int jp = 0; jp < 16; jp++) acc1[jp] = 0ull;
#pragma unroll
    for (int kc = 0; kc < 2; kc++) {
#pragma unroll
        for (int t = 0; t < 9; t++) {
            const int ti = TI9[t], tj = TJ9[t];
#pragma unroll
            for (int kk = 0; kk < 16; kk++) {
                const int k = kc * 16 + kk;
                float af = (ti == 0) ? a0[k] : (ti == 1) ? a1[k] : a2[k];
                ull av = splat2(af);
#pragma unroll
                for (int q = 0; q < 8; q++) {
                    ulonglong2 w = cW1v[tj][k * 8 + q];
                    fma2(acc1[2 * q],     av, w.x);
                    fma2(acc1[2 * q + 1], av, w.y);
                }
            }
        }
    }

    float h0[HID], h1[HID], h2[HID];
#pragma unroll
    for (int jp = 0; jp < 16; jp++) {
        float2 v = unpack2(acc1[jp]);
        int j0 = 2 * jp;
        float hv0 = c19_f32(__fadd_rn(v.x, sB1[j0]),     sC[j0],     sR[j0]);
        float hv1 = c19_f32(__fadd_rn(v.y, sB1[j0 + 1]), sC[j0 + 1], sR[j0 + 1]);
        bf16_split(hv0, h0[j0], h1[j0], h2[j0]);
        bf16_split(hv1, h0[j0 + 1], h1[j0 + 1], h2[j0 + 1]);
    }

    // ---- gemm2 ----
    ull acc2[8];
#pragma unroll
    for (int dp = 0; dp < 8; dp++) acc2[dp] = 0ull;
#pragma unroll
    for (int kc = 0; kc < 2; kc++) {
#pragma unroll
        for (int t = 0; t < 9; t++) {
            const int ti = TI9[t], tj = TJ9[t];
#pragma unroll
            for (int kk = 0; kk < 16; kk++) {
                const int j = kc * 16 + kk;
                float hf = (ti == 0) ? h0[j] : (ti == 1) ? h1[j] : h2[j];
                ull hv = splat2(hf);
#pragma unroll
                for (int q = 0; q < 4; q++) {
                    ulonglong2 w = cW2v[tj][j * 4 + q];
                    fma2(acc2[2 * q],     hv, w.x);
                    fma2(acc2[2 * q + 1], hv, w.y);
                }
            }
        }
    }

    float* dst = final_level ? (fout + (size_t)n * DIM)
                             : (out + ((size_t)n * P + p) * DIM);
#pragma unroll
    for (int dp = 0; dp < 8; dp++) {
        float2 v = unpack2(acc2[dp]);
        dst[2 * dp]     = __fadd_rn(v.x, sB2[2 * dp]);
        dst[2 * dp + 1] = __fadd_rn(v.y, sB2[2 * dp + 1]);
    }
}

// ============ Blend: out = 0.5*(anchor + emul) ============
__global__ void blend_kernel(float* __restrict__ out)
{
    int i = blockIdx.x * 256 + threadIdx.x;
    if (i < N_SEQ * DIM)
        out[i] = 0.5f * (g_fds[i] + g_fem[i]);
}

extern "C" void kernel_launch(void* const* d_in, const int* in_sizes, int n_in,
                              void* d_out, int out_size)
{
    const float* x   = (const float*)d_in[0];
    const float* W1  = (const float*)d_in[1];
    const float* b1  = (const float*)d_in[2];
    const float* W2  = (const float*)d_in[3];
    const float* b2  = (const float*)d_in[4];
    const float* c   = (const float*)d_in[5];
    const float* rho = (const float*)d_in[6];
    float* out = (float*)d_out;

    kq_quant<<<1, 256>>>(W1, W2);

    // Copy device-computed weights into constant memory (D2D async: capturable).
    void *p1, *p2, *p3, *p4;
    cudaGetSymbolAddress(&p1, g_W1s);
    cudaGetSymbolAddress(&p2, g_W2s);
    cudaGetSymbolAddress(&p3, g_W1q);
    cudaGetSymbolAddress(&p4, g_W2q);
    cudaMemcpyToSymbolAsync(cW1v, p1, sizeof(g_W1s), 0, cudaMemcpyDeviceToDevice, 0);
    cudaMemcpyToSymbolAsync(cW2v, p2, sizeof(g_W2s), 0, cudaMemcpyDeviceToDevice, 0);
    cudaMemcpyToSymbolAsync(cW1a, p3, sizeof(g_W1q), 0, cudaMemcpyDeviceToDevice, 0);
    cudaMemcpyToSymbolAsync(cW2a, p4, sizeof(g_W2q), 0, cudaMemcpyDeviceToDevice, 0);

    // --- fp32 anchor pipeline ---
    const int smem1 = (WBASE + 1024 * VSTRIDE + 512 * VSTRIDE) * 4;
    const int smem2 = (WBASE + 512 * VSTRIDE + 256 * VSTRIDE) * 4;
    cudaFuncSetAttribute(k1_tree, cudaFuncAttributeMaxDynamicSharedMemorySize, smem1);
    cudaFuncSetAttribute(k2_top,  cudaFuncAttributeMaxDynamicSharedMemorySize, smem2);
    k1_tree<<<N_SEQ, 256, smem1>>>(x, b1, b2, c, rho);
    k2_top<<<N_SEQ / 16, 256, smem2>>>(b1, b2, c, rho);

    // --- bf16x9 emulated pipeline (bit-identical values) ---
    float* emA;  cudaGetSymbolAddress((void**)&emA, g_emA);
    float* emB;  cudaGetSymbolAddress((void**)&emB, g_emB);
    float* fem;  cudaGetSymbolAddress((void**)&fem, g_fem);
    {
        const float* src = nullptr;
        int P = T_LEN / 2, first = 1, use_a = 1;
        while (P >= 1) {
            int fin = (P == 1);
            float* dst = use_a ? emA : emB;
            long long total = (long long)N_SEQ * P;
            int blocks = (int)((total + 255) / 256);
            level_em<<<blocks, 256>>>(x, src, dst, fem, P, first, fin, b1, b2, c, rho);
            src = dst; first = 0; use_a ^= 1; P >>= 1;
        }
    }

    blend_kernel<<<(N_SEQ * DIM + 255) / 256, 256>>>(out);
}